// round 1
// baseline (speedup 1.0000x reference)
#include <cuda_runtime.h>

#define NB 8
#define NN 2048
#define NF 512

// Scratch (allocation-free rule: __device__ globals)
__device__ float g_s[NB * NN];                       // 64 KB
__device__ float g_y[(size_t)NB * NN * NF];          // 32 MB

// ---------------------------------------------------------------------------
// Kernel 1: s_i = rsqrt( 1 + sum_j A[b,i,j] )
// ---------------------------------------------------------------------------
__global__ void degree_kernel(const float* __restrict__ A) {
    const int row = blockIdx.x;                      // 0 .. NB*NN-1
    const float* a = A + (size_t)row * NN;
    float sum = 0.f;
    for (int j = threadIdx.x; j < NN; j += blockDim.x) sum += a[j];
    __shared__ float red[8];
    #pragma unroll
    for (int o = 16; o; o >>= 1) sum += __shfl_down_sync(0xffffffff, sum, o);
    if ((threadIdx.x & 31) == 0) red[threadIdx.x >> 5] = sum;
    __syncthreads();
    if (threadIdx.x == 0) {
        float t = 1.0f;  // self-loop (identity)
        #pragma unroll
        for (int w = 0; w < 8; w++) t += red[w];
        g_s[row] = rsqrtf(t);
    }
}

// ---------------------------------------------------------------------------
// Tiled SGEMM core: BM=128, BN=64, BK=16, 256 threads, 8x4 per-thread tile.
// All problem dims divide the tiles exactly (2048/128, 512/64, K%16==0).
// ---------------------------------------------------------------------------
#define BM 128
#define BN 64
#define BK 16

// Kernel 2: y[b,m,n] = s[b,m] * ( sum_k X[b,m,k]*W[k,n] + bias[n] )
__global__ __launch_bounds__(256, 2)
void xw_kernel(const float* __restrict__ X, const float* __restrict__ W,
               const float* __restrict__ bias) {
    __shared__ float As[BK][BM];
    __shared__ float Bs[BK][BN];

    const int bb = blockIdx.z;
    const int m0 = blockIdx.y * BM;
    const int n0 = blockIdx.x * BN;
    const float* Xp = X + ((size_t)bb * NN + m0) * NF;

    const int tid = threadIdx.x;
    const int tx = tid & 15;        // 0..15 -> 4 cols each
    const int ty = tid >> 4;        // 0..15 -> 8 rows each

    float acc[8][4] = {};

    for (int k0 = 0; k0 < NF; k0 += BK) {
        // X tile: 128 rows x 16 cols = 512 float4, 2 per thread
        #pragma unroll
        for (int i = 0; i < 2; i++) {
            int id = tid + i * 256;
            int r = id >> 2, c4 = id & 3;
            float4 v = *(const float4*)(Xp + (size_t)r * NF + k0 + c4 * 4);
            As[c4 * 4 + 0][r] = v.x; As[c4 * 4 + 1][r] = v.y;
            As[c4 * 4 + 2][r] = v.z; As[c4 * 4 + 3][r] = v.w;
        }
        // W tile: 16 rows x 64 cols = 256 float4, 1 per thread
        {
            int r = tid >> 4, c4 = tid & 15;
            float4 v = *(const float4*)(W + (size_t)(k0 + r) * NF + n0 + c4 * 4);
            *(float4*)&Bs[r][c4 * 4] = v;
        }
        __syncthreads();
        #pragma unroll
        for (int k = 0; k < BK; k++) {
            float a[8];
            #pragma unroll
            for (int i = 0; i < 8; i++) a[i] = As[k][ty * 8 + i];
            float4 b4 = *(const float4*)&Bs[k][tx * 4];
            float bv[4] = {b4.x, b4.y, b4.z, b4.w};
            #pragma unroll
            for (int i = 0; i < 8; i++)
                #pragma unroll
                for (int j = 0; j < 4; j++) acc[i][j] += a[i] * bv[j];
        }
        __syncthreads();
    }

    #pragma unroll
    for (int i = 0; i < 8; i++) {
        int row = m0 + ty * 8 + i;
        float s = g_s[bb * NN + row];
        float* yrow = g_y + ((size_t)bb * NN + row) * NF;
        #pragma unroll
        for (int j = 0; j < 4; j++) {
            int col = n0 + tx * 4 + j;
            yrow[col] = s * (acc[i][j] + bias[col]);
        }
    }
}

// Kernel 3: out[b,m,n] = s[b,m] * ( sum_k A[b,m,k]*y[b,k,n] + y[b,m,n] )
__global__ __launch_bounds__(256, 2)
void agg_kernel(const float* __restrict__ A, float* __restrict__ out) {
    __shared__ float As[BK][BM];
    __shared__ float Bs[BK][BN];

    const int bb = blockIdx.z;
    const int m0 = blockIdx.y * BM;
    const int n0 = blockIdx.x * BN;
    const float* Ap = A + ((size_t)bb * NN + m0) * NN;
    const float* Yb = g_y + (size_t)bb * NN * NF;

    const int tid = threadIdx.x;
    const int tx = tid & 15;
    const int ty = tid >> 4;

    float acc[8][4] = {};

    for (int k0 = 0; k0 < NN; k0 += BK) {
        #pragma unroll
        for (int i = 0; i < 2; i++) {
            int id = tid + i * 256;
            int r = id >> 2, c4 = id & 3;
            float4 v = *(const float4*)(Ap + (size_t)r * NN + k0 + c4 * 4);
            As[c4 * 4 + 0][r] = v.x; As[c4 * 4 + 1][r] = v.y;
            As[c4 * 4 + 2][r] = v.z; As[c4 * 4 + 3][r] = v.w;
        }
        {
            int r = tid >> 4, c4 = tid & 15;
            float4 v = *(const float4*)(Yb + (size_t)(k0 + r) * NF + n0 + c4 * 4);
            *(float4*)&Bs[r][c4 * 4] = v;
        }
        __syncthreads();
        #pragma unroll
        for (int k = 0; k < BK; k++) {
            float a[8];
            #pragma unroll
            for (int i = 0; i < 8; i++) a[i] = As[k][ty * 8 + i];
            float4 b4 = *(const float4*)&Bs[k][tx * 4];
            float bv[4] = {b4.x, b4.y, b4.z, b4.w};
            #pragma unroll
            for (int i = 0; i < 8; i++)
                #pragma unroll
                for (int j = 0; j < 4; j++) acc[i][j] += a[i] * bv[j];
        }
        __syncthreads();
    }

    #pragma unroll
    for (int i = 0; i < 8; i++) {
        int row = m0 + ty * 8 + i;
        float s = g_s[bb * NN + row];
        const float* yrow = Yb + (size_t)row * NF;
        float* orow = out + ((size_t)bb * NN + row) * NF;
        #pragma unroll
        for (int j = 0; j < 4; j++) {
            int col = n0 + tx * 4 + j;
            orow[col] = s * (acc[i][j] + yrow[col]);
        }
    }
}

// ---------------------------------------------------------------------------
extern "C" void kernel_launch(void* const* d_in, const int* in_sizes, int n_in,
                              void* d_out, int out_size) {
    const float* X    = (const float*)d_in[0];   // [8,2048,512]
    const float* A    = (const float*)d_in[1];   // [8,2048,2048]
    const float* W    = (const float*)d_in[2];   // [512,512]
    const float* bias = (const float*)d_in[3];   // [512]
    float* out = (float*)d_out;                  // [8,2048,512]

    // 1) degree scales
    degree_kernel<<<NB * NN, 256>>>(A);

    // 2) y = s * (XW + b)
    {
        dim3 grid(NF / BN, NN / BM, NB);
        xw_kernel<<<grid, 256>>>(X, W, bias);
    }

    // 3) out = s * (A@y + y)
    {
        dim3 grid(NF / BN, NN / BM, NB);
        agg_kernel<<<grid, 256>>>(A, out);
    }
}

// round 3
// speedup vs baseline: 2.4148x; 2.4148x over previous
#include <cuda_runtime.h>
#include <cuda_bf16.h>
#include <cstdint>

#define NB 8
#define NN 2048
#define NF 512

// ---------------- device scratch (allocation-free rule) ----------------
__device__ float g_s[NB * NN];
__device__ __nv_bfloat16 g_Ah[(size_t)NB * NN * NN];   // 64 MB
__device__ __nv_bfloat16 g_Al[(size_t)NB * NN * NN];   // 64 MB
__device__ __nv_bfloat16 g_Xh[(size_t)NB * NN * NF];   // 16 MB
__device__ __nv_bfloat16 g_Xl[(size_t)NB * NN * NF];
__device__ __nv_bfloat16 g_WTh[(size_t)NF * NF];       // W transposed [f][k]
__device__ __nv_bfloat16 g_WTl[(size_t)NF * NF];
__device__ __nv_bfloat16 g_yTh[(size_t)NB * NF * NN];  // y transposed [b][f][node]
__device__ __nv_bfloat16 g_yTl[(size_t)NB * NF * NN];

// ---------------- helpers ----------------
__device__ __forceinline__ uint32_t smem_u32(const void* p) {
    uint32_t a;
    asm("{ .reg .u64 t; cvta.to.shared.u64 t, %1; cvt.u32.u64 %0, t; }"
        : "=r"(a) : "l"(p));
    return a;
}
__device__ __forceinline__ uint32_t swz(uint32_t off) { return off ^ ((off >> 3) & 0x70); }

#define CP16(dst, src) \
    asm volatile("cp.async.cg.shared.global [%0], [%1], 16;" :: "r"(dst), "l"(src))
#define CP_COMMIT() asm volatile("cp.async.commit_group;" ::: "memory")

#define LDSM4(r0, r1, r2, r3, addr) \
    asm volatile("ldmatrix.sync.aligned.m8n8.x4.shared.b16 {%0,%1,%2,%3}, [%4];" \
                 : "=r"(r0), "=r"(r1), "=r"(r2), "=r"(r3) : "r"(addr))

#define MMA16816(c, a, b) \
    asm volatile("mma.sync.aligned.m16n8k16.row.col.f32.bf16.bf16.f32 " \
                 "{%0,%1,%2,%3}, {%4,%5,%6,%7}, {%8,%9}, {%0,%1,%2,%3};" \
                 : "+f"((c)[0]), "+f"((c)[1]), "+f"((c)[2]), "+f"((c)[3]) \
                 : "r"((a)[0]), "r"((a)[1]), "r"((a)[2]), "r"((a)[3]), \
                   "r"((b)[0]), "r"((b)[1]))

// ---------------- conversion kernels ----------------
// A -> bf16 hi/lo, fused with degree: s = rsqrt(1 + rowsum(A))
__global__ void convA_kernel(const float* __restrict__ A) {
    const int row = blockIdx.x;                    // 0 .. NB*NN-1
    const float* src = A + (size_t)row * NN;
    __nv_bfloat16* dh = g_Ah + (size_t)row * NN;
    __nv_bfloat16* dl = g_Al + (size_t)row * NN;
    const int t = threadIdx.x;                     // 256, 8 elems each
    float4 v0 = *(const float4*)(src + t * 8);
    float4 v1 = *(const float4*)(src + t * 8 + 4);
    float v[8] = {v0.x, v0.y, v0.z, v0.w, v1.x, v1.y, v1.z, v1.w};
    alignas(16) __nv_bfloat16 h[8];
    alignas(16) __nv_bfloat16 l[8];
    float sum = 0.f;
    #pragma unroll
    for (int i = 0; i < 8; i++) {
        sum += v[i];
        h[i] = __float2bfloat16(v[i]);
        l[i] = __float2bfloat16(v[i] - __bfloat162float(h[i]));
    }
    *(uint4*)(dh + t * 8) = *(uint4*)h;
    *(uint4*)(dl + t * 8) = *(uint4*)l;
    __shared__ float red[8];
    #pragma unroll
    for (int o = 16; o; o >>= 1) sum += __shfl_down_sync(0xffffffff, sum, o);
    if ((t & 31) == 0) red[t >> 5] = sum;
    __syncthreads();
    if (t == 0) {
        float tot = 1.0f;
        #pragma unroll
        for (int w = 0; w < 8; w++) tot += red[w];
        g_s[row] = rsqrtf(tot);
    }
}

__global__ void convX_kernel(const float* __restrict__ X) {
    const int row = blockIdx.x;
    const float* src = X + (size_t)row * NF;
    __nv_bfloat16* dh = g_Xh + (size_t)row * NF;
    __nv_bfloat16* dl = g_Xl + (size_t)row * NF;
    const int t = threadIdx.x;                     // 64, 8 elems each
    float4 v0 = *(const float4*)(src + t * 8);
    float4 v1 = *(const float4*)(src + t * 8 + 4);
    float v[8] = {v0.x, v0.y, v0.z, v0.w, v1.x, v1.y, v1.z, v1.w};
    alignas(16) __nv_bfloat16 h[8];
    alignas(16) __nv_bfloat16 l[8];
    #pragma unroll
    for (int i = 0; i < 8; i++) {
        h[i] = __float2bfloat16(v[i]);
        l[i] = __float2bfloat16(v[i] - __bfloat162float(h[i]));
    }
    *(uint4*)(dh + t * 8) = *(uint4*)h;
    *(uint4*)(dl + t * 8) = *(uint4*)l;
}

__global__ void convW_kernel(const float* __restrict__ W) {
    const int f = blockIdx.x;                      // 512
    const int k = threadIdx.x;                     // 512
    float v = W[(size_t)k * NF + f];
    __nv_bfloat16 hi = __float2bfloat16(v);
    __nv_bfloat16 lo = __float2bfloat16(v - __bfloat162float(hi));
    g_WTh[(size_t)f * NF + k] = hi;
    g_WTl[(size_t)f * NF + k] = lo;
}

// ---------------- HMMA GEMM ----------------
// CTA tile: M=128, N=128, Kchunk=64. 8 warps = 4(m) x 2(n); warp tile 32x64.
// A[m][k], B[n][k] bf16 hi/lo in SW128-swizzled smem (128B rows).
// D = (Ah+Al)(Bh+Bl) approx AhBh + AhBl + AlBh   (3-term split)
#define OFF_AH 0
#define OFF_AL 16384
#define OFF_BH 32768
#define OFF_BL 49152
#define STAGE_BYTES 65536
#define SMEM_TOTAL (2 * STAGE_BYTES)

template <int KTOT, bool IS_XW>
__global__ __launch_bounds__(256, 1)
void gemm_kernel(const float* __restrict__ bias, float* __restrict__ out) {
    constexpr int NCH = KTOT / 64;
    extern __shared__ __align__(1024) char smem[];
    const uint32_t sb = smem_u32(smem);

    const int tid = threadIdx.x;
    const int wid = tid >> 5;
    const int lane = tid & 31;
    const int wm = wid & 3;        // 4 m-tiles of 32
    const int wn = wid >> 2;       // 2 n-tiles of 64

    const int bb = blockIdx.z;
    const int m0 = blockIdx.y * 128;
    const int n0 = blockIdx.x * 128;

    const __nv_bfloat16 *pAh, *pAl, *pBh, *pBl;
    size_t lda, ldb;
    if (IS_XW) {
        lda = NF; ldb = NF;
        pAh = g_Xh + ((size_t)bb * NN + m0) * NF;
        pAl = g_Xl + ((size_t)bb * NN + m0) * NF;
        pBh = g_WTh + (size_t)n0 * NF;
        pBl = g_WTl + (size_t)n0 * NF;
    } else {
        lda = NN; ldb = NN;
        pAh = g_Ah + ((size_t)bb * NN + m0) * NN;
        pAl = g_Al + ((size_t)bb * NN + m0) * NN;
        pBh = g_yTh + ((size_t)bb * NF + n0) * NN;
        pBl = g_yTl + ((size_t)bb * NF + n0) * NN;
    }

    // each thread loads 4 x 16B per array per stage (128 rows x 8 chunks / 256 thr)
    auto load_stage = [&](int s, int chunk) {
        const uint32_t base = sb + (uint32_t)s * STAGE_BYTES;
        const int k0 = chunk * 64;
        #pragma unroll
        for (int i = 0; i < 4; i++) {
            int g = tid + i * 256;
            int r = g >> 3, c = g & 7;
            uint32_t so = swz((uint32_t)(r * 128 + c * 16));
            const char* gh = (const char*)(pAh + (size_t)r * lda + k0) + c * 16;
            const char* gl = (const char*)(pAl + (size_t)r * lda + k0) + c * 16;
            CP16(base + OFF_AH + so, gh);
            CP16(base + OFF_AL + so, gl);
            const char* bh_ = (const char*)(pBh + (size_t)r * ldb + k0) + c * 16;
            const char* bl_ = (const char*)(pBl + (size_t)r * ldb + k0) + c * 16;
            CP16(base + OFF_BH + so, bh_);
            CP16(base + OFF_BL + so, bl_);
        }
        CP_COMMIT();
    };

    float c[2][8][4];
    #pragma unroll
    for (int i = 0; i < 2; i++)
        #pragma unroll
        for (int j = 0; j < 8; j++)
            #pragma unroll
            for (int k = 0; k < 4; k++) c[i][j][k] = 0.f;

    // ldmatrix lane->address row/col components (byte offsets within tile)
    const int a_row = wm * 32 + (lane & 15);            // + mf*16
    const int a_kb  = (lane >> 4) * 16;                  // bytes: (lane>>4)*8 elems *2
    const int b_row = wn * 64 + ((lane >> 4) << 3) + (lane & 7);  // + nb*16
    const int b_kb  = ((lane >> 3) & 1) * 16;

    load_stage(0, 0);

    #pragma unroll 1
    for (int i = 0; i < NCH; i++) {
        const int s = i & 1;
        if (i + 1 < NCH) {
            load_stage(s ^ 1, i + 1);
            asm volatile("cp.async.wait_group 1;" ::: "memory");
        } else {
            asm volatile("cp.async.wait_group 0;" ::: "memory");
        }
        __syncthreads();

        const uint32_t base = sb + (uint32_t)s * STAGE_BYTES;
        #pragma unroll
        for (int ks = 0; ks < 4; ks++) {
            uint32_t ah[2][4], al[2][4], bh[8][2], bl[8][2];
            #pragma unroll
            for (int mf = 0; mf < 2; mf++) {
                uint32_t off = swz((uint32_t)((a_row + mf * 16) * 128 + ks * 32 + a_kb));
                LDSM4(ah[mf][0], ah[mf][1], ah[mf][2], ah[mf][3], base + OFF_AH + off);
                LDSM4(al[mf][0], al[mf][1], al[mf][2], al[mf][3], base + OFF_AL + off);
            }
            #pragma unroll
            for (int nb = 0; nb < 4; nb++) {
                uint32_t off = swz((uint32_t)((b_row + nb * 16) * 128 + ks * 32 + b_kb));
                LDSM4(bh[2*nb][0], bh[2*nb][1], bh[2*nb+1][0], bh[2*nb+1][1],
                      base + OFF_BH + off);
                LDSM4(bl[2*nb][0], bl[2*nb][1], bl[2*nb+1][0], bl[2*nb+1][1],
                      base + OFF_BL + off);
            }
            #pragma unroll
            for (int mf = 0; mf < 2; mf++)
                #pragma unroll
                for (int nf = 0; nf < 8; nf++) {
                    MMA16816(c[mf][nf], ah[mf], bh[nf]);
                    MMA16816(c[mf][nf], ah[mf], bl[nf]);
                    MMA16816(c[mf][nf], al[mf], bh[nf]);
                }
        }
        __syncthreads();
    }

    // ---------------- epilogue ----------------
    const int g4 = lane >> 2;
    const int tq = lane & 3;
    #pragma unroll
    for (int mf = 0; mf < 2; mf++) {
        #pragma unroll
        for (int half = 0; half < 2; half++) {
            const int m = m0 + wm * 32 + mf * 16 + g4 + half * 8;  // global node row
            const float s = g_s[bb * NN + m];
            if (IS_XW) {
                #pragma unroll
                for (int nf = 0; nf < 8; nf++) {
                    #pragma unroll
                    for (int e = 0; e < 2; e++) {
                        const int f = n0 + wn * 64 + nf * 8 + tq * 2 + e;
                        float y = s * (c[mf][nf][half * 2 + e] + bias[f]);
                        __nv_bfloat16 hi = __float2bfloat16(y);
                        __nv_bfloat16 lo = __float2bfloat16(y - __bfloat162float(hi));
                        const size_t idx = ((size_t)bb * NF + f) * NN + m;
                        g_yTh[idx] = hi;
                        g_yTl[idx] = lo;
                    }
                }
            } else {
                float* orow = out + ((size_t)bb * NN + m) * NF;
                #pragma unroll
                for (int nf = 0; nf < 8; nf++) {
                    const int f = n0 + wn * 64 + nf * 8 + tq * 2;
                    float2 o;
                    const size_t iy0 = ((size_t)bb * NF + f) * NN + m;
                    float y0 = __bfloat162float(g_yTh[iy0]) + __bfloat162float(g_yTl[iy0]);
                    float y1 = __bfloat162float(g_yTh[iy0 + NN]) + __bfloat162float(g_yTl[iy0 + NN]);
                    o.x = s * (c[mf][nf][half * 2 + 0] + y0);
                    o.y = s * (c[mf][nf][half * 2 + 1] + y1);
                    *(float2*)(orow + f) = o;
                }
            }
        }
    }
}

// ---------------- launch ----------------
extern "C" void kernel_launch(void* const* d_in, const int* in_sizes, int n_in,
                              void* d_out, int out_size) {
    const float* X    = (const float*)d_in[0];   // [8,2048,512]
    const float* A    = (const float*)d_in[1];   // [8,2048,2048]
    const float* W    = (const float*)d_in[2];   // [512,512]
    const float* bias = (const float*)d_in[3];   // [512]
    float* out = (float*)d_out;                  // [8,2048,512]

    cudaFuncSetAttribute(gemm_kernel<NF, true>,
                         cudaFuncAttributeMaxDynamicSharedMemorySize, SMEM_TOTAL);
    cudaFuncSetAttribute(gemm_kernel<NN, false>,
                         cudaFuncAttributeMaxDynamicSharedMemorySize, SMEM_TOTAL);

    convA_kernel<<<NB * NN, 256>>>(A);           // A -> bf16 hi/lo + degree scales
    convX_kernel<<<NB * NN, 64>>>(X);            // X -> bf16 hi/lo
    convW_kernel<<<NF, NF>>>(W);                 // W -> transposed bf16 hi/lo

    dim3 grid(NF / 128, NN / 128, NB);           // (4, 16, 8) = 512 CTAs
    gemm_kernel<NF, true><<<grid, 256, SMEM_TOTAL>>>(bias, out);   // y = s*(XW+b) -> yT hi/lo
    gemm_kernel<NN, false><<<grid, 256, SMEM_TOTAL>>>(bias, out);  // out = s*(A@y + y)
}

// round 4
// speedup vs baseline: 2.6186x; 1.0844x over previous
#include <cuda_runtime.h>
#include <cuda_bf16.h>
#include <cstdint>

#define NB 8
#define NN 2048
#define NF 512

// ---------------- device scratch (allocation-free rule) ----------------
__device__ float g_s[NB * NN];
__device__ __nv_bfloat16 g_Ah[(size_t)NB * NN * NN];   // A+I hi, 64 MB
__device__ __nv_bfloat16 g_Al[(size_t)NB * NN * NN];   // A+I lo
__device__ __nv_bfloat16 g_Xh[(size_t)NB * NN * NF];
__device__ __nv_bfloat16 g_Xl[(size_t)NB * NN * NF];
__device__ __nv_bfloat16 g_Wh[(size_t)NF * NF];        // W row-major [k][f]
__device__ __nv_bfloat16 g_Wl[(size_t)NF * NF];
__device__ __nv_bfloat16 g_yh[(size_t)NB * NN * NF];   // y row-major [node][f]
__device__ __nv_bfloat16 g_yl[(size_t)NB * NN * NF];

// ---------------- helpers ----------------
__device__ __forceinline__ uint32_t smem_u32(const void* p) {
    uint32_t a;
    asm("{ .reg .u64 t; cvta.to.shared.u64 t, %1; cvt.u32.u64 %0, t; }"
        : "=r"(a) : "l"(p));
    return a;
}
__device__ __forceinline__ uint32_t swzA(uint32_t off) { return off ^ ((off >> 3) & 0x70); }

#define CP16(dst, src) \
    asm volatile("cp.async.cg.shared.global [%0], [%1], 16;" :: "r"(dst), "l"(src))
#define CP_COMMIT() asm volatile("cp.async.commit_group;" ::: "memory")

#define LDSM4(r0, r1, r2, r3, addr) \
    asm volatile("ldmatrix.sync.aligned.m8n8.x4.shared.b16 {%0,%1,%2,%3}, [%4];" \
                 : "=r"(r0), "=r"(r1), "=r"(r2), "=r"(r3) : "r"(addr))
#define LDSM4T(r0, r1, r2, r3, addr) \
    asm volatile("ldmatrix.sync.aligned.m8n8.x4.trans.shared.b16 {%0,%1,%2,%3}, [%4];" \
                 : "=r"(r0), "=r"(r1), "=r"(r2), "=r"(r3) : "r"(addr))

#define MMA16816(c, a, b) \
    asm volatile("mma.sync.aligned.m16n8k16.row.col.f32.bf16.bf16.f32 " \
                 "{%0,%1,%2,%3}, {%4,%5,%6,%7}, {%8,%9}, {%0,%1,%2,%3};" \
                 : "+f"((c)[0]), "+f"((c)[1]), "+f"((c)[2]), "+f"((c)[3]) \
                 : "r"((a)[0]), "r"((a)[1]), "r"((a)[2]), "r"((a)[3]), \
                   "r"((b)[0]), "r"((b)[1]))

// ---------------- conversion kernels ----------------
// A -> (A+I) bf16 hi/lo, fused degree: s = rsqrt(rowsum(A)+1)
__global__ void convA_kernel(const float* __restrict__ A) {
    const int row = blockIdx.x;                    // 0 .. NB*NN-1
    const int node = row & (NN - 1);               // row within batch
    const float* src = A + (size_t)row * NN;
    __nv_bfloat16* dh = g_Ah + (size_t)row * NN;
    __nv_bfloat16* dl = g_Al + (size_t)row * NN;
    const int t = threadIdx.x;                     // 256 thr, 8 elems each
    float4 v0 = *(const float4*)(src + t * 8);
    float4 v1 = *(const float4*)(src + t * 8 + 4);
    float v[8] = {v0.x, v0.y, v0.z, v0.w, v1.x, v1.y, v1.z, v1.w};
    // self-loop: A_hat = A + I
    if (node >= t * 8 && node < t * 8 + 8) v[node - t * 8] += 1.0f;
    alignas(16) __nv_bfloat16 h[8];
    alignas(16) __nv_bfloat16 l[8];
    float sum = 0.f;
    #pragma unroll
    for (int i = 0; i < 8; i++) {
        sum += v[i];
        h[i] = __float2bfloat16(v[i]);
        l[i] = __float2bfloat16(v[i] - __bfloat162float(h[i]));
    }
    *(uint4*)(dh + t * 8) = *(uint4*)h;
    *(uint4*)(dl + t * 8) = *(uint4*)l;
    __shared__ float red[8];
    #pragma unroll
    for (int o = 16; o; o >>= 1) sum += __shfl_down_sync(0xffffffff, sum, o);
    if ((t & 31) == 0) red[t >> 5] = sum;
    __syncthreads();
    if (t == 0) {
        float tot = 0.0f;
        #pragma unroll
        for (int w = 0; w < 8; w++) tot += red[w];
        g_s[row] = rsqrtf(tot);
    }
}

// generic fp32 -> bf16 hi/lo for rows of NF elements (X and W)
__global__ void conv_hl_kernel(const float* __restrict__ src_,
                               __nv_bfloat16* __restrict__ dh_,
                               __nv_bfloat16* __restrict__ dl_) {
    const int row = blockIdx.x;
    const float* src = src_ + (size_t)row * NF;
    __nv_bfloat16* dh = dh_ + (size_t)row * NF;
    __nv_bfloat16* dl = dl_ + (size_t)row * NF;
    const int t = threadIdx.x;                     // 64 thr, 8 elems each
    float4 v0 = *(const float4*)(src + t * 8);
    float4 v1 = *(const float4*)(src + t * 8 + 4);
    float v[8] = {v0.x, v0.y, v0.z, v0.w, v1.x, v1.y, v1.z, v1.w};
    alignas(16) __nv_bfloat16 h[8];
    alignas(16) __nv_bfloat16 l[8];
    #pragma unroll
    for (int i = 0; i < 8; i++) {
        h[i] = __float2bfloat16(v[i]);
        l[i] = __float2bfloat16(v[i] - __bfloat162float(h[i]));
    }
    *(uint4*)(dh + t * 8) = *(uint4*)h;
    *(uint4*)(dl + t * 8) = *(uint4*)l;
}

// ---------------- HMMA GEMM ----------------
// CTA tile M=128, N=128, Kchunk=64. 8 warps = 4(m) x 2(n); warp tile 32x64.
// A [m][k] K-major (SW128). B [k][n] row-major (custom swizzle), trans-LDSM.
// 3-term split: D = AhBh + AhBl + AlBh. 3-stage cp.async pipeline.
#define OFF_AH 0
#define OFF_AL 16384
#define OFF_BH 32768
#define OFF_BL 49152
#define STAGE_BYTES 65536
#define NSTAGE 3
#define SMEM_TOTAL (NSTAGE * STAGE_BYTES)

template <int KTOT, bool IS_XW>
__global__ __launch_bounds__(256, 1)
void gemm_kernel(const float* __restrict__ bias, float* __restrict__ out) {
    constexpr int NCH = KTOT / 64;
    extern __shared__ __align__(1024) char smem[];
    const uint32_t sb = smem_u32(smem);

    const int tid = threadIdx.x;
    const int wid = tid >> 5;
    const int lane = tid & 31;
    const int wm = wid & 3;        // 4 m-tiles of 32
    const int wn = wid >> 2;       // 2 n-tiles of 64

    const int bb = blockIdx.z;
    const int m0 = blockIdx.y * 128;
    const int n0 = blockIdx.x * 128;

    const __nv_bfloat16 *pAh, *pAl, *pBh, *pBl;
    size_t lda;
    if (IS_XW) {
        lda = NF;
        pAh = g_Xh + ((size_t)bb * NN + m0) * NF;
        pAl = g_Xl + ((size_t)bb * NN + m0) * NF;
        pBh = g_Wh + n0;                         // [k][n] row-major, ld = NF
        pBl = g_Wl + n0;
    } else {
        lda = NN;
        pAh = g_Ah + ((size_t)bb * NN + m0) * NN;
        pAl = g_Al + ((size_t)bb * NN + m0) * NN;
        pBh = g_yh + (size_t)bb * NN * NF + n0;  // y [node][f], ld = NF
        pBl = g_yl + (size_t)bb * NN * NF + n0;
    }

    auto load_stage = [&](int s, int chunk) {
        const uint32_t base = sb + (uint32_t)s * STAGE_BYTES;
        const int k0 = chunk * 64;
        #pragma unroll
        for (int i = 0; i < 4; i++) {              // A: 128 rows x 8 x 16B
            int g = tid + i * 256;
            int r = g >> 3, c = g & 7;
            uint32_t so = swzA((uint32_t)(r * 128 + c * 16));
            CP16(base + OFF_AH + so, (const char*)(pAh + (size_t)r * lda + k0) + c * 16);
            CP16(base + OFF_AL + so, (const char*)(pAl + (size_t)r * lda + k0) + c * 16);
        }
        #pragma unroll
        for (int i = 0; i < 4; i++) {              // B: 64 k-rows x 16 x 16B
            int g = tid + i * 256;
            int k = g >> 4, c = g & 15;
            uint32_t so = (uint32_t)(k * 256 + ((c * 16) ^ ((k & 7) << 4)));
            CP16(base + OFF_BH + so, (const char*)(pBh + (size_t)(k0 + k) * NF) + c * 16);
            CP16(base + OFF_BL + so, (const char*)(pBl + (size_t)(k0 + k) * NF) + c * 16);
        }
        CP_COMMIT();
    };

    float c[2][8][4];
    #pragma unroll
    for (int i = 0; i < 2; i++)
        #pragma unroll
        for (int j = 0; j < 8; j++)
            #pragma unroll
            for (int k = 0; k < 4; k++) c[i][j][k] = 0.f;

    // A ldsm (non-trans x4): 16m x 16k
    const int a_row = wm * 32 + (lane & 15);
    const int a_kb  = (lane >> 4) * 16;
    // B ldsm (trans x4): 16k x 16n from [k][n] rows of 256B
    const int b_krow = (lane & 7) + (lane & 8);             // 0..15
    const uint32_t b_swz = (uint32_t)(lane & 7) << 4;
    const int b_nbyte = wn * 128 + ((lane >> 4) & 1) * 16;  // + nb*32

    load_stage(0, 0);
    load_stage(1, 1);

    #pragma unroll 1
    for (int i = 0; i < NCH; i++) {
        if (i + 1 < NCH) asm volatile("cp.async.wait_group 1;" ::: "memory");
        else             asm volatile("cp.async.wait_group 0;" ::: "memory");
        __syncthreads();
        if (i + 2 < NCH) load_stage((i + 2) % NSTAGE, i + 2);

        const uint32_t base = sb + (uint32_t)(i % NSTAGE) * STAGE_BYTES;
        #pragma unroll
        for (int ks = 0; ks < 4; ks++) {
            uint32_t ah[2][4], al[2][4], bh[8][2], bl[8][2];
            #pragma unroll
            for (int mf = 0; mf < 2; mf++) {
                uint32_t off = swzA((uint32_t)((a_row + mf * 16) * 128 + ks * 32 + a_kb));
                LDSM4(ah[mf][0], ah[mf][1], ah[mf][2], ah[mf][3], base + OFF_AH + off);
                LDSM4(al[mf][0], al[mf][1], al[mf][2], al[mf][3], base + OFF_AL + off);
            }
            #pragma unroll
            for (int nb = 0; nb < 4; nb++) {
                uint32_t addr = base + (uint32_t)((ks * 16 + b_krow) * 256) +
                                ((uint32_t)(b_nbyte + nb * 32) ^ b_swz);
                LDSM4T(bh[2*nb][0], bh[2*nb][1], bh[2*nb+1][0], bh[2*nb+1][1],
                       addr + OFF_BH);
                LDSM4T(bl[2*nb][0], bl[2*nb][1], bl[2*nb+1][0], bl[2*nb+1][1],
                       addr + OFF_BL);
            }
            #pragma unroll
            for (int mf = 0; mf < 2; mf++)
                #pragma unroll
                for (int nf = 0; nf < 8; nf++) {
                    MMA16816(c[mf][nf], ah[mf], bh[nf]);
                    MMA16816(c[mf][nf], ah[mf], bl[nf]);
                    MMA16816(c[mf][nf], al[mf], bh[nf]);
                }
        }
    }

    // ---------------- epilogue ----------------
    const int g4 = lane >> 2;
    const int tq = lane & 3;
    #pragma unroll
    for (int mf = 0; mf < 2; mf++) {
        #pragma unroll
        for (int half = 0; half < 2; half++) {
            const int m = m0 + wm * 32 + mf * 16 + g4 + half * 8;
            const float s = g_s[bb * NN + m];
            if (IS_XW) {
                __nv_bfloat16* yh = g_yh + ((size_t)bb * NN + m) * NF;
                __nv_bfloat16* yl = g_yl + ((size_t)bb * NN + m) * NF;
                #pragma unroll
                for (int nf = 0; nf < 8; nf++) {
                    const int f = n0 + wn * 64 + nf * 8 + tq * 2;
                    float2 bs = *(const float2*)(bias + f);
                    float y0 = s * (c[mf][nf][half * 2 + 0] + bs.x);
                    float y1 = s * (c[mf][nf][half * 2 + 1] + bs.y);
                    __nv_bfloat16 h0 = __float2bfloat16(y0);
                    __nv_bfloat16 h1 = __float2bfloat16(y1);
                    __nv_bfloat162 hv; hv.x = h0; hv.y = h1;
                    __nv_bfloat162 lv;
                    lv.x = __float2bfloat16(y0 - __bfloat162float(h0));
                    lv.y = __float2bfloat16(y1 - __bfloat162float(h1));
                    *(__nv_bfloat162*)(yh + f) = hv;
                    *(__nv_bfloat162*)(yl + f) = lv;
                }
            } else {
                float* orow = out + ((size_t)bb * NN + m) * NF;
                #pragma unroll
                for (int nf = 0; nf < 8; nf++) {
                    const int f = n0 + wn * 64 + nf * 8 + tq * 2;
                    float2 o;
                    o.x = s * c[mf][nf][half * 2 + 0];
                    o.y = s * c[mf][nf][half * 2 + 1];
                    *(float2*)(orow + f) = o;
                }
            }
        }
    }
}

// ---------------- launch ----------------
extern "C" void kernel_launch(void* const* d_in, const int* in_sizes, int n_in,
                              void* d_out, int out_size) {
    const float* X    = (const float*)d_in[0];   // [8,2048,512]
    const float* A    = (const float*)d_in[1];   // [8,2048,2048]
    const float* W    = (const float*)d_in[2];   // [512,512]
    const float* bias = (const float*)d_in[3];   // [512]
    float* out = (float*)d_out;                  // [8,2048,512]

    cudaFuncSetAttribute(gemm_kernel<NF, true>,
                         cudaFuncAttributeMaxDynamicSharedMemorySize, SMEM_TOTAL);
    cudaFuncSetAttribute(gemm_kernel<NN, false>,
                         cudaFuncAttributeMaxDynamicSharedMemorySize, SMEM_TOTAL);

    // pointers to __device__ globals usable directly from host launch args?
    // No — must take addresses via symbols on device; instead pass via kernels
    // that reference the globals internally. conv_hl needs src/dst args:
    __nv_bfloat16 *dXh, *dXl, *dWh, *dWl;
    cudaGetSymbolAddress((void**)&dXh, g_Xh);
    cudaGetSymbolAddress((void**)&dXl, g_Xl);
    cudaGetSymbolAddress((void**)&dWh, g_Wh);
    cudaGetSymbolAddress((void**)&dWl, g_Wl);

    convA_kernel<<<NB * NN, 256>>>(A);                     // A+I -> hi/lo + degree
    conv_hl_kernel<<<NB * NN, 64>>>(X, dXh, dXl);          // X -> hi/lo
    conv_hl_kernel<<<NF, 64>>>(W, dWh, dWl);               // W -> hi/lo (row-major)

    dim3 grid(NF / 128, NN / 128, NB);                     // (4, 16, 8)
    gemm_kernel<NF, true><<<grid, 256, SMEM_TOTAL>>>(bias, out);   // y = s*(XW+b)
    gemm_kernel<NN, false><<<grid, 256, SMEM_TOTAL>>>(bias, out);  // out = s*(Ahat@y)
}

// round 5
// speedup vs baseline: 2.7483x; 1.0495x over previous
#include <cuda_runtime.h>
#include <cuda_bf16.h>
#include <cstdint>

#define NB 8
#define NN 2048
#define NF 512

// ---------------- device scratch (allocation-free rule) ----------------
__device__ float g_s[NB * NN];
__device__ __nv_bfloat16 g_Ah[(size_t)NB * NN * NN];   // A+I hi, 64 MB
__device__ __nv_bfloat16 g_Al[(size_t)NB * NN * NN];   // A+I lo
__device__ __nv_bfloat16 g_Xh[(size_t)NB * NN * NF];
__device__ __nv_bfloat16 g_Xl[(size_t)NB * NN * NF];
__device__ __nv_bfloat16 g_Wh[(size_t)NF * NF];        // W row-major [k][f]
__device__ __nv_bfloat16 g_Wl[(size_t)NF * NF];
__device__ __nv_bfloat16 g_yh[(size_t)NB * NN * NF];   // y row-major [node][f]
__device__ __nv_bfloat16 g_yl[(size_t)NB * NN * NF];

// ---------------- helpers ----------------
__device__ __forceinline__ uint32_t smem_u32(const void* p) {
    uint32_t a;
    asm("{ .reg .u64 t; cvta.to.shared.u64 t, %1; cvt.u32.u64 %0, t; }"
        : "=r"(a) : "l"(p));
    return a;
}
__device__ __forceinline__ uint32_t swzA(uint32_t off) { return off ^ ((off >> 3) & 0x70); }

#define CP16(dst, src) \
    asm volatile("cp.async.cg.shared.global [%0], [%1], 16;" :: "r"(dst), "l"(src))
#define CP_COMMIT() asm volatile("cp.async.commit_group;" ::: "memory")

#define LDSM4(r0, r1, r2, r3, addr) \
    asm volatile("ldmatrix.sync.aligned.m8n8.x4.shared.b16 {%0,%1,%2,%3}, [%4];" \
                 : "=r"(r0), "=r"(r1), "=r"(r2), "=r"(r3) : "r"(addr))
#define LDSM4T(r0, r1, r2, r3, addr) \
    asm volatile("ldmatrix.sync.aligned.m8n8.x4.trans.shared.b16 {%0,%1,%2,%3}, [%4];" \
                 : "=r"(r0), "=r"(r1), "=r"(r2), "=r"(r3) : "r"(addr))

#define MMA16816(c, a, b) \
    asm volatile("mma.sync.aligned.m16n8k16.row.col.f32.bf16.bf16.f32 " \
                 "{%0,%1,%2,%3}, {%4,%5,%6,%7}, {%8,%9}, {%0,%1,%2,%3};" \
                 : "+f"((c)[0]), "+f"((c)[1]), "+f"((c)[2]), "+f"((c)[3]) \
                 : "r"((a)[0]), "r"((a)[1]), "r"((a)[2]), "r"((a)[3]), \
                   "r"((b)[0]), "r"((b)[1]))

// ---------------- conversion kernels ----------------
// A -> (A+I) bf16 hi/lo, fused degree: s = rsqrt(rowsum(A)+1)
__global__ void convA_kernel(const float* __restrict__ A) {
    const int row = blockIdx.x;                    // 0 .. NB*NN-1
    const int node = row & (NN - 1);
    const float* src = A + (size_t)row * NN;
    __nv_bfloat16* dh = g_Ah + (size_t)row * NN;
    __nv_bfloat16* dl = g_Al + (size_t)row * NN;
    const int t = threadIdx.x;                     // 256 thr, 8 elems each
    float4 v0 = *(const float4*)(src + t * 8);
    float4 v1 = *(const float4*)(src + t * 8 + 4);
    float v[8] = {v0.x, v0.y, v0.z, v0.w, v1.x, v1.y, v1.z, v1.w};
    if (node >= t * 8 && node < t * 8 + 8) v[node - t * 8] += 1.0f;   // +I
    alignas(16) __nv_bfloat16 h[8];
    alignas(16) __nv_bfloat16 l[8];
    float sum = 0.f;
    #pragma unroll
    for (int i = 0; i < 8; i++) {
        sum += v[i];
        h[i] = __float2bfloat16(v[i]);
        l[i] = __float2bfloat16(v[i] - __bfloat162float(h[i]));
    }
    *(uint4*)(dh + t * 8) = *(uint4*)h;
    *(uint4*)(dl + t * 8) = *(uint4*)l;
    __shared__ float red[8];
    #pragma unroll
    for (int o = 16; o; o >>= 1) sum += __shfl_down_sync(0xffffffff, sum, o);
    if ((t & 31) == 0) red[t >> 5] = sum;
    __syncthreads();
    if (t == 0) {
        float tot = 0.0f;
        #pragma unroll
        for (int w = 0; w < 8; w++) tot += red[w];
        g_s[row] = rsqrtf(tot);
    }
}

__global__ void conv_hl_kernel(const float* __restrict__ src_,
                               __nv_bfloat16* __restrict__ dh_,
                               __nv_bfloat16* __restrict__ dl_) {
    const int row = blockIdx.x;
    const float* src = src_ + (size_t)row * NF;
    __nv_bfloat16* dh = dh_ + (size_t)row * NF;
    __nv_bfloat16* dl = dl_ + (size_t)row * NF;
    const int t = threadIdx.x;                     // 64 thr, 8 elems each
    float4 v0 = *(const float4*)(src + t * 8);
    float4 v1 = *(const float4*)(src + t * 8 + 4);
    float v[8] = {v0.x, v0.y, v0.z, v0.w, v1.x, v1.y, v1.z, v1.w};
    alignas(16) __nv_bfloat16 h[8];
    alignas(16) __nv_bfloat16 l[8];
    #pragma unroll
    for (int i = 0; i < 8; i++) {
        h[i] = __float2bfloat16(v[i]);
        l[i] = __float2bfloat16(v[i] - __bfloat162float(h[i]));
    }
    *(uint4*)(dh + t * 8) = *(uint4*)h;
    *(uint4*)(dl + t * 8) = *(uint4*)l;
}

// ---------------- HMMA GEMM ----------------
// CTA tile M=128, N=256, Kchunk=64. 8 warps = 2(m) x 4(n); warp tile 64x64.
// A [m][k] K-major pitch 128B (SW128 swizzle). B [k][n] row-major pitch 512B
// with XOR swizzle, trans-LDSM. 3-term split: D = AhBh + AhBl + AlBh.
// 2-stage cp.async pipeline (96 KB/stage).
#define OFF_AH 0
#define OFF_AL 16384
#define OFF_BH 32768
#define OFF_BL 65536
#define STAGE_BYTES 98304
#define SMEM_TOTAL (2 * STAGE_BYTES)

template <int KTOT, bool IS_XW>
__global__ __launch_bounds__(256, 1)
void gemm_kernel(const float* __restrict__ bias, float* __restrict__ out) {
    constexpr int NCH = KTOT / 64;
    extern __shared__ __align__(1024) char smem[];
    const uint32_t sb = smem_u32(smem);

    const int tid = threadIdx.x;
    const int wid = tid >> 5;
    const int lane = tid & 31;
    const int wm = wid >> 2;       // 2 m-tiles of 64
    const int wn = wid & 3;        // 4 n-tiles of 64

    const int bb = blockIdx.z;
    const int m0 = blockIdx.y * 128;
    const int n0 = blockIdx.x * 256;

    const __nv_bfloat16 *pAh, *pAl, *pBh, *pBl;
    size_t lda;
    if (IS_XW) {
        lda = NF;
        pAh = g_Xh + ((size_t)bb * NN + m0) * NF;
        pAl = g_Xl + ((size_t)bb * NN + m0) * NF;
        pBh = g_Wh + n0;                         // [k][n], ld = NF
        pBl = g_Wl + n0;
    } else {
        lda = NN;
        pAh = g_Ah + ((size_t)bb * NN + m0) * NN;
        pAl = g_Al + ((size_t)bb * NN + m0) * NN;
        pBh = g_yh + (size_t)bb * NN * NF + n0;  // y [node][f], ld = NF
        pBl = g_yl + (size_t)bb * NN * NF + n0;
    }

    auto load_stage = [&](int s, int chunk) {
        const uint32_t base = sb + (uint32_t)s * STAGE_BYTES;
        const int k0 = chunk * 64;
        #pragma unroll
        for (int i = 0; i < 4; i++) {              // A: 128 rows x 8 x 16B
            int g = tid + i * 256;
            int r = g >> 3, c = g & 7;
            uint32_t so = swzA((uint32_t)(r * 128 + c * 16));
            CP16(base + OFF_AH + so, (const char*)(pAh + (size_t)r * lda + k0) + c * 16);
            CP16(base + OFF_AL + so, (const char*)(pAl + (size_t)r * lda + k0) + c * 16);
        }
        #pragma unroll
        for (int i = 0; i < 8; i++) {              // B: 64 k-rows x 32 x 16B
            int g = tid + i * 256;
            int k = g >> 5, c = g & 31;
            uint32_t so = (uint32_t)(k * 512 + ((c * 16) ^ ((k & 7) << 4)));
            CP16(base + OFF_BH + so, (const char*)(pBh + (size_t)(k0 + k) * NF) + c * 16);
            CP16(base + OFF_BL + so, (const char*)(pBl + (size_t)(k0 + k) * NF) + c * 16);
        }
        CP_COMMIT();
    };

    float c[4][8][4];
    #pragma unroll
    for (int i = 0; i < 4; i++)
        #pragma unroll
        for (int j = 0; j < 8; j++)
            #pragma unroll
            for (int k = 0; k < 4; k++) c[i][j][k] = 0.f;

    // A ldsm (non-trans x4): 16m x 16k per call
    const int a_row = wm * 64 + (lane & 15);
    const int a_kb  = (lane >> 4) * 16;
    // B ldsm (trans x4): 16k x 16n per call; rows pitch 512B
    const int b_krow = lane & 15;
    const uint32_t b_swz = (uint32_t)(b_krow & 7) << 4;
    const int b_nbyte = wn * 128 + (lane >> 4) * 16;     // + nb*32

    load_stage(0, 0);

    #pragma unroll 1
    for (int i = 0; i < NCH; i++) {
        asm volatile("cp.async.wait_group 0;" ::: "memory");
        __syncthreads();
        if (i + 1 < NCH) load_stage((i + 1) & 1, i + 1);

        const uint32_t base = sb + (uint32_t)(i & 1) * STAGE_BYTES;
        #pragma unroll
        for (int ks = 0; ks < 4; ks++) {
            uint32_t ah[4][4], al[4][4];
            #pragma unroll
            for (int mf = 0; mf < 4; mf++) {
                uint32_t off = swzA((uint32_t)((a_row + mf * 16) * 128 + ks * 32 + a_kb));
                LDSM4(ah[mf][0], ah[mf][1], ah[mf][2], ah[mf][3], base + OFF_AH + off);
                LDSM4(al[mf][0], al[mf][1], al[mf][2], al[mf][3], base + OFF_AL + off);
            }
            #pragma unroll
            for (int nb = 0; nb < 4; nb++) {
                uint32_t bh[2][2], bl[2][2];
                uint32_t addr = base + (uint32_t)((ks * 16 + b_krow) * 512) +
                                ((uint32_t)(b_nbyte + nb * 32) ^ b_swz);
                LDSM4T(bh[0][0], bh[0][1], bh[1][0], bh[1][1], addr + OFF_BH);
                LDSM4T(bl[0][0], bl[0][1], bl[1][0], bl[1][1], addr + OFF_BL);
                #pragma unroll
                for (int mf = 0; mf < 4; mf++) {
                    MMA16816(c[mf][2*nb],   ah[mf], bh[0]);
                    MMA16816(c[mf][2*nb],   ah[mf], bl[0]);
                    MMA16816(c[mf][2*nb],   al[mf], bh[0]);
                    MMA16816(c[mf][2*nb+1], ah[mf], bh[1]);
                    MMA16816(c[mf][2*nb+1], ah[mf], bl[1]);
                    MMA16816(c[mf][2*nb+1], al[mf], bh[1]);
                }
            }
        }
    }

    // ---------------- epilogue ----------------
    const int g4 = lane >> 2;
    const int tq = lane & 3;
    #pragma unroll
    for (int mf = 0; mf < 4; mf++) {
        #pragma unroll
        for (int half = 0; half < 2; half++) {
            const int m = m0 + wm * 64 + mf * 16 + g4 + half * 8;
            const float s = g_s[bb * NN + m];
            if (IS_XW) {
                __nv_bfloat16* yh = g_yh + ((size_t)bb * NN + m) * NF;
                __nv_bfloat16* yl = g_yl + ((size_t)bb * NN + m) * NF;
                #pragma unroll
                for (int nf = 0; nf < 8; nf++) {
                    const int f = n0 + wn * 64 + nf * 8 + tq * 2;
                    float2 bs = *(const float2*)(bias + f);
                    float y0 = s * (c[mf][nf][half * 2 + 0] + bs.x);
                    float y1 = s * (c[mf][nf][half * 2 + 1] + bs.y);
                    __nv_bfloat16 h0 = __float2bfloat16(y0);
                    __nv_bfloat16 h1 = __float2bfloat16(y1);
                    __nv_bfloat162 hv; hv.x = h0; hv.y = h1;
                    __nv_bfloat162 lv;
                    lv.x = __float2bfloat16(y0 - __bfloat162float(h0));
                    lv.y = __float2bfloat16(y1 - __bfloat162float(h1));
                    *(__nv_bfloat162*)(yh + f) = hv;
                    *(__nv_bfloat162*)(yl + f) = lv;
                }
            } else {
                float* orow = out + ((size_t)bb * NN + m) * NF;
                #pragma unroll
                for (int nf = 0; nf < 8; nf++) {
                    const int f = n0 + wn * 64 + nf * 8 + tq * 2;
                    float2 o;
                    o.x = s * c[mf][nf][half * 2 + 0];
                    o.y = s * c[mf][nf][half * 2 + 1];
                    *(float2*)(orow + f) = o;
                }
            }
        }
    }
}

// ---------------- launch ----------------
extern "C" void kernel_launch(void* const* d_in, const int* in_sizes, int n_in,
                              void* d_out, int out_size) {
    const float* X    = (const float*)d_in[0];   // [8,2048,512]
    const float* A    = (const float*)d_in[1];   // [8,2048,2048]
    const float* W    = (const float*)d_in[2];   // [512,512]
    const float* bias = (const float*)d_in[3];   // [512]
    float* out = (float*)d_out;                  // [8,2048,512]

    cudaFuncSetAttribute(gemm_kernel<NF, true>,
                         cudaFuncAttributeMaxDynamicSharedMemorySize, SMEM_TOTAL);
    cudaFuncSetAttribute(gemm_kernel<NN, false>,
                         cudaFuncAttributeMaxDynamicSharedMemorySize, SMEM_TOTAL);

    __nv_bfloat16 *dXh, *dXl, *dWh, *dWl;
    cudaGetSymbolAddress((void**)&dXh, g_Xh);
    cudaGetSymbolAddress((void**)&dXl, g_Xl);
    cudaGetSymbolAddress((void**)&dWh, g_Wh);
    cudaGetSymbolAddress((void**)&dWl, g_Wl);

    convA_kernel<<<NB * NN, 256>>>(A);                     // A+I -> hi/lo + degree
    conv_hl_kernel<<<NB * NN, 64>>>(X, dXh, dXl);          // X -> hi/lo
    conv_hl_kernel<<<NF, 64>>>(W, dWh, dWl);               // W -> hi/lo

    dim3 grid(NF / 256, NN / 128, NB);                     // (2, 16, 8) = 256 CTAs
    gemm_kernel<NF, true><<<grid, 256, SMEM_TOTAL>>>(bias, out);   // y = s*(XW+b)
    gemm_kernel<NN, false><<<grid, 256, SMEM_TOTAL>>>(bias, out);  // out = s*(Ahat@y)
}

// round 6
// speedup vs baseline: 2.7576x; 1.0034x over previous
#include <cuda_runtime.h>
#include <cuda_bf16.h>
#include <cstdint>

#define NB 8
#define NN 2048
#define NF 512

// ---------------- device scratch (allocation-free rule) ----------------
__device__ float g_s[NB * NN];
__device__ __nv_bfloat16 g_Ah[(size_t)NB * NN * NN];   // A+I hi, 64 MB
__device__ __nv_bfloat16 g_Al[(size_t)NB * NN * NN];   // A+I lo
__device__ __nv_bfloat16 g_Xh[(size_t)NB * NN * NF];
__device__ __nv_bfloat16 g_Xl[(size_t)NB * NN * NF];
__device__ __nv_bfloat16 g_Wh[(size_t)NF * NF];        // W row-major [k][f]
__device__ __nv_bfloat16 g_Wl[(size_t)NF * NF];
__device__ __nv_bfloat16 g_yh[(size_t)NB * NN * NF];   // y row-major [node][f]
__device__ __nv_bfloat16 g_yl[(size_t)NB * NN * NF];

// ---------------- helpers ----------------
__device__ __forceinline__ uint32_t smem_u32(const void* p) {
    uint32_t a;
    asm("{ .reg .u64 t; cvta.to.shared.u64 t, %1; cvt.u32.u64 %0, t; }"
        : "=r"(a) : "l"(p));
    return a;
}
__device__ __forceinline__ uint32_t swzA(uint32_t off) { return off ^ ((off >> 3) & 0x70); }

#define CP16(dst, src) \
    asm volatile("cp.async.cg.shared.global [%0], [%1], 16;" :: "r"(dst), "l"(src))
#define CP_COMMIT() asm volatile("cp.async.commit_group;" ::: "memory")

#define LDSM4(r0, r1, r2, r3, addr) \
    asm volatile("ldmatrix.sync.aligned.m8n8.x4.shared.b16 {%0,%1,%2,%3}, [%4];" \
                 : "=r"(r0), "=r"(r1), "=r"(r2), "=r"(r3) : "r"(addr))
#define LDSM4T(r0, r1, r2, r3, addr) \
    asm volatile("ldmatrix.sync.aligned.m8n8.x4.trans.shared.b16 {%0,%1,%2,%3}, [%4];" \
                 : "=r"(r0), "=r"(r1), "=r"(r2), "=r"(r3) : "r"(addr))

// NOT volatile: register constraints fully describe the op; lets ptxas schedule.
#define MMA16816(c, a, b) \
    asm("mma.sync.aligned.m16n8k16.row.col.f32.bf16.bf16.f32 " \
        "{%0,%1,%2,%3}, {%4,%5,%6,%7}, {%8,%9}, {%0,%1,%2,%3};" \
        : "+f"((c)[0]), "+f"((c)[1]), "+f"((c)[2]), "+f"((c)[3]) \
        : "r"((a)[0]), "r"((a)[1]), "r"((a)[2]), "r"((a)[3]), \
          "r"((b)[0]), "r"((b)[1]))

// ---------------- conversion kernels ----------------
// A -> (A+I) bf16 hi/lo, fused degree: s = rsqrt(rowsum(A)+1)
__global__ void convA_kernel(const float* __restrict__ A) {
    const int row = blockIdx.x;                    // 0 .. NB*NN-1
    const int node = row & (NN - 1);
    const float* src = A + (size_t)row * NN;
    __nv_bfloat16* dh = g_Ah + (size_t)row * NN;
    __nv_bfloat16* dl = g_Al + (size_t)row * NN;
    const int t = threadIdx.x;                     // 256 thr, 8 elems each
    float4 v0 = *(const float4*)(src + t * 8);
    float4 v1 = *(const float4*)(src + t * 8 + 4);
    float v[8] = {v0.x, v0.y, v0.z, v0.w, v1.x, v1.y, v1.z, v1.w};
    if (node >= t * 8 && node < t * 8 + 8) v[node - t * 8] += 1.0f;   // +I
    alignas(16) __nv_bfloat16 h[8];
    alignas(16) __nv_bfloat16 l[8];
    float sum = 0.f;
    #pragma unroll
    for (int i = 0; i < 8; i++) {
        sum += v[i];
        h[i] = __float2bfloat16(v[i]);
        l[i] = __float2bfloat16(v[i] - __bfloat162float(h[i]));
    }
    *(uint4*)(dh + t * 8) = *(uint4*)h;
    *(uint4*)(dl + t * 8) = *(uint4*)l;
    __shared__ float red[8];
    #pragma unroll
    for (int o = 16; o; o >>= 1) sum += __shfl_down_sync(0xffffffff, sum, o);
    if ((t & 31) == 0) red[t >> 5] = sum;
    __syncthreads();
    if (t == 0) {
        float tot = 0.0f;
        #pragma unroll
        for (int w = 0; w < 8; w++) tot += red[w];
        g_s[row] = rsqrtf(tot);
    }
}

__global__ void conv_hl_kernel(const float* __restrict__ src_,
                               __nv_bfloat16* __restrict__ dh_,
                               __nv_bfloat16* __restrict__ dl_) {
    const int row = blockIdx.x;
    const float* src = src_ + (size_t)row * NF;
    __nv_bfloat16* dh = dh_ + (size_t)row * NF;
    __nv_bfloat16* dl = dl_ + (size_t)row * NF;
    const int t = threadIdx.x;                     // 64 thr, 8 elems each
    float4 v0 = *(const float4*)(src + t * 8);
    float4 v1 = *(const float4*)(src + t * 8 + 4);
    float v[8] = {v0.x, v0.y, v0.z, v0.w, v1.x, v1.y, v1.z, v1.w};
    alignas(16) __nv_bfloat16 h[8];
    alignas(16) __nv_bfloat16 l[8];
    #pragma unroll
    for (int i = 0; i < 8; i++) {
        h[i] = __float2bfloat16(v[i]);
        l[i] = __float2bfloat16(v[i] - __bfloat162float(h[i]));
    }
    *(uint4*)(dh + t * 8) = *(uint4*)h;
    *(uint4*)(dl + t * 8) = *(uint4*)l;
}

// ---------------- HMMA GEMM ----------------
// CTA tile M=128, N=256, Kchunk=64. 8 warps = 2(m) x 4(n); warp tile 64x64.
// A [m][k] K-major pitch 128B (SW128). B [k][n] row-major pitch 512B with XOR
// swizzle, trans-LDSM. 3-term split D = AhBh + AhBl + AlBh, MMAs interleaved
// so dependent accumulations are >= 8 issues apart.
#define OFF_AH 0
#define OFF_AL 16384
#define OFF_BH 32768
#define OFF_BL 65536
#define STAGE_BYTES 98304
#define SMEM_TOTAL (2 * STAGE_BYTES)

template <int KTOT, bool IS_XW>
__global__ __launch_bounds__(256, 1)
void gemm_kernel(const float* __restrict__ bias, float* __restrict__ out) {
    constexpr int NCH = KTOT / 64;
    extern __shared__ __align__(1024) char smem[];
    const uint32_t sb = smem_u32(smem);

    const int tid = threadIdx.x;
    const int wid = tid >> 5;
    const int lane = tid & 31;
    const int wm = wid >> 2;       // 2 m-tiles of 64
    const int wn = wid & 3;        // 4 n-tiles of 64

    const int bb = blockIdx.z;
    const int m0 = blockIdx.y * 128;
    const int n0 = blockIdx.x * 256;

    const __nv_bfloat16 *pAh, *pAl, *pBh, *pBl;
    size_t lda;
    if (IS_XW) {
        lda = NF;
        pAh = g_Xh + ((size_t)bb * NN + m0) * NF;
        pAl = g_Xl + ((size_t)bb * NN + m0) * NF;
        pBh = g_Wh + n0;
        pBl = g_Wl + n0;
    } else {
        lda = NN;
        pAh = g_Ah + ((size_t)bb * NN + m0) * NN;
        pAl = g_Al + ((size_t)bb * NN + m0) * NN;
        pBh = g_yh + (size_t)bb * NN * NF + n0;
        pBl = g_yl + (size_t)bb * NN * NF + n0;
    }

    auto load_stage = [&](int s, int chunk) {
        const uint32_t base = sb + (uint32_t)s * STAGE_BYTES;
        const int k0 = chunk * 64;
        #pragma unroll
        for (int i = 0; i < 4; i++) {              // A: 128 rows x 8 x 16B
            int g = tid + i * 256;
            int r = g >> 3, c = g & 7;
            uint32_t so = swzA((uint32_t)(r * 128 + c * 16));
            CP16(base + OFF_AH + so, (const char*)(pAh + (size_t)r * lda + k0) + c * 16);
            CP16(base + OFF_AL + so, (const char*)(pAl + (size_t)r * lda + k0) + c * 16);
        }
        #pragma unroll
        for (int i = 0; i < 8; i++) {              // B: 64 k-rows x 32 x 16B
            int g = tid + i * 256;
            int k = g >> 5, c = g & 31;
            uint32_t so = (uint32_t)(k * 512 + ((c * 16) ^ ((k & 7) << 4)));
            CP16(base + OFF_BH + so, (const char*)(pBh + (size_t)(k0 + k) * NF) + c * 16);
            CP16(base + OFF_BL + so, (const char*)(pBl + (size_t)(k0 + k) * NF) + c * 16);
        }
        CP_COMMIT();
    };

    float c[4][8][4];
    #pragma unroll
    for (int i = 0; i < 4; i++)
        #pragma unroll
        for (int j = 0; j < 8; j++)
            #pragma unroll
            for (int k = 0; k < 4; k++) c[i][j][k] = 0.f;

    const int a_row = wm * 64 + (lane & 15);
    const int a_kb  = (lane >> 4) * 16;
    const int b_krow = lane & 15;
    const uint32_t b_swz = (uint32_t)(b_krow & 7) << 4;
    const int b_nbyte = wn * 128 + (lane >> 4) * 16;

    load_stage(0, 0);

    #pragma unroll 1
    for (int i = 0; i < NCH; i++) {
        asm volatile("cp.async.wait_group 0;" ::: "memory");
        __syncthreads();
        if (i + 1 < NCH) load_stage((i + 1) & 1, i + 1);

        const uint32_t base = sb + (uint32_t)(i & 1) * STAGE_BYTES;
        #pragma unroll
        for (int ks = 0; ks < 4; ks++) {
            uint32_t ah[4][4], al[4][4];
            #pragma unroll
            for (int mf = 0; mf < 4; mf++) {
                uint32_t off = swzA((uint32_t)((a_row + mf * 16) * 128 + ks * 32 + a_kb));
                LDSM4(ah[mf][0], ah[mf][1], ah[mf][2], ah[mf][3], base + OFF_AH + off);
                LDSM4(al[mf][0], al[mf][1], al[mf][2], al[mf][3], base + OFF_AL + off);
            }
            #pragma unroll
            for (int nb = 0; nb < 4; nb++) {
                uint32_t bh[2][2], bl[2][2];
                uint32_t addr = base + (uint32_t)((ks * 16 + b_krow) * 512) +
                                ((uint32_t)(b_nbyte + nb * 32) ^ b_swz);
                LDSM4T(bh[0][0], bh[0][1], bh[1][0], bh[1][1], addr + OFF_BH);
                LDSM4T(bl[0][0], bl[0][1], bl[1][0], bl[1][1], addr + OFF_BL);
                // interleaved: dependent MMAs on the same accumulator are 8 apart
                #pragma unroll
                for (int mf = 0; mf < 4; mf++) MMA16816(c[mf][2*nb],   ah[mf], bh[0]);
                #pragma unroll
                for (int mf = 0; mf < 4; mf++) MMA16816(c[mf][2*nb+1], ah[mf], bh[1]);
                #pragma unroll
                for (int mf = 0; mf < 4; mf++) MMA16816(c[mf][2*nb],   ah[mf], bl[0]);
                #pragma unroll
                for (int mf = 0; mf < 4; mf++) MMA16816(c[mf][2*nb+1], ah[mf], bl[1]);
                #pragma unroll
                for (int mf = 0; mf < 4; mf++) MMA16816(c[mf][2*nb],   al[mf], bh[0]);
                #pragma unroll
                for (int mf = 0; mf < 4; mf++) MMA16816(c[mf][2*nb+1], al[mf], bh[1]);
            }
        }
    }

    // ---------------- epilogue ----------------
    const int g4 = lane >> 2;
    const int tq = lane & 3;
    #pragma unroll
    for (int mf = 0; mf < 4; mf++) {
        #pragma unroll
        for (int half = 0; half < 2; half++) {
            const int m = m0 + wm * 64 + mf * 16 + g4 + half * 8;
            const float s = g_s[bb * NN + m];
            if (IS_XW) {
                __nv_bfloat16* yh = g_yh + ((size_t)bb * NN + m) * NF;
                __nv_bfloat16* yl = g_yl + ((size_t)bb * NN + m) * NF;
                #pragma unroll
                for (int nf = 0; nf < 8; nf++) {
                    const int f = n0 + wn * 64 + nf * 8 + tq * 2;
                    float2 bs = *(const float2*)(bias + f);
                    float y0 = s * (c[mf][nf][half * 2 + 0] + bs.x);
                    float y1 = s * (c[mf][nf][half * 2 + 1] + bs.y);
                    __nv_bfloat16 h0 = __float2bfloat16(y0);
                    __nv_bfloat16 h1 = __float2bfloat16(y1);
                    __nv_bfloat162 hv; hv.x = h0; hv.y = h1;
                    __nv_bfloat162 lv;
                    lv.x = __float2bfloat16(y0 - __bfloat162float(h0));
                    lv.y = __float2bfloat16(y1 - __bfloat162float(h1));
                    *(__nv_bfloat162*)(yh + f) = hv;
                    *(__nv_bfloat162*)(yl + f) = lv;
                }
            } else {
                float* orow = out + ((size_t)bb * NN + m) * NF;
                #pragma unroll
                for (int nf = 0; nf < 8; nf++) {
                    const int f = n0 + wn * 64 + nf * 8 + tq * 2;
                    float2 o;
                    o.x = s * c[mf][nf][half * 2 + 0];
                    o.y = s * c[mf][nf][half * 2 + 1];
                    *(float2*)(orow + f) = o;
                }
            }
        }
    }
}

// ---------------- launch ----------------
extern "C" void kernel_launch(void* const* d_in, const int* in_sizes, int n_in,
                              void* d_out, int out_size) {
    const float* X    = (const float*)d_in[0];   // [8,2048,512]
    const float* A    = (const float*)d_in[1];   // [8,2048,2048]
    const float* W    = (const float*)d_in[2];   // [512,512]
    const float* bias = (const float*)d_in[3];   // [512]
    float* out = (float*)d_out;                  // [8,2048,512]

    cudaFuncSetAttribute(gemm_kernel<NF, true>,
                         cudaFuncAttributeMaxDynamicSharedMemorySize, SMEM_TOTAL);
    cudaFuncSetAttribute(gemm_kernel<NN, false>,
                         cudaFuncAttributeMaxDynamicSharedMemorySize, SMEM_TOTAL);

    __nv_bfloat16 *dXh, *dXl, *dWh, *dWl;
    cudaGetSymbolAddress((void**)&dXh, g_Xh);
    cudaGetSymbolAddress((void**)&dXl, g_Xl);
    cudaGetSymbolAddress((void**)&dWh, g_Wh);
    cudaGetSymbolAddress((void**)&dWl, g_Wl);

    convA_kernel<<<NB * NN, 256>>>(A);                     // A+I -> hi/lo + degree
    conv_hl_kernel<<<NB * NN, 64>>>(X, dXh, dXl);          // X -> hi/lo
    conv_hl_kernel<<<NF, 64>>>(W, dWh, dWl);               // W -> hi/lo

    dim3 grid(NF / 256, NN / 128, NB);                     // (2, 16, 8) = 256 CTAs
    gemm_kernel<NF, true><<<grid, 256, SMEM_TOTAL>>>(bias, out);   // y = s*(XW+b)
    gemm_kernel<NN, false><<<grid, 256, SMEM_TOTAL>>>(bias, out);  // out = s*(Ahat@y)
}